// round 10
// baseline (speedup 1.0000x reference)
#include <cuda_runtime.h>
#include <cuda_bf16.h>
#include <cstdint>

// FirstSpikeDetector: out[b][t] = 1 iff spike_train[b][t] is the first nonzero
// in row b, else 0. Input values are exact 0.0f / 1.0f.
//
// R10: hide the detection read under the memset.
//   Branch A (main stream):  1D full memset of out (128MB @ ~6.4 TB/s, ~20us).
//   Branch B (side stream):  detector reads input only (8MB) and parks each
//                            row's first-spike index in __device__ scratch.
//                            Zero bytes written to out -> no race, true overlap.
//   Join, then scatter node: one thread per row writes 1.0f at the parked
//                            index (idx written for EVERY row every call ->
//                            deterministic across graph replays).
// R7 arithmetic: bench 27.1 = memset 20.3 + detector 6.7 (serial). Moving the
// detector off the critical path leaves memset + small scatter.

static constexpr int T    = 2048;    // time steps per row
static constexpr int TV4  = T / 4;   // float4s per row (512)
static constexpr int ROWS = 16384;

__device__ int g_first_idx[ROWS];    // -1 = no spike; else first-spike index

__global__ void __launch_bounds__(256)
first_spike_detect(const float* __restrict__ in, int rows)
{
    const int gtid = blockIdx.x * blockDim.x + threadIdx.x;
    const int warp = gtid >> 5;
    const int lane = gtid & 31;
    if (warp >= rows) return;

    const float4* __restrict__ row_in =
        reinterpret_cast<const float4*>(in) + (size_t)warp * TV4;

    // ---- scan elements 0..127 (1 x LDG.128 per lane) ----
    float4 v = row_in[lane];
    const bool any = (v.x != 0.0f) | (v.y != 0.0f) | (v.z != 0.0f) | (v.w != 0.0f);
    const unsigned m = __ballot_sync(0xffffffffu, any);

    if (m != 0u) {
        const int src = __ffs(m) - 1;
        if (lane == src) {
            int sub;
            if      (v.x != 0.0f) sub = 0;
            else if (v.y != 0.0f) sub = 1;
            else if (v.z != 0.0f) sub = 2;
            else                  sub = 3;
            g_first_idx[warp] = (src << 2) + sub;
        }
        return;
    }

    // Rare path (P ~ 1.4e-6 per row): keep scanning chunks of 128 elements.
    #pragma unroll 1
    for (int base = 128; base < T; base += 128) {
        float4 u = row_in[(base >> 2) + lane];
        bool a2 = (u.x != 0.0f) | (u.y != 0.0f) | (u.z != 0.0f) | (u.w != 0.0f);
        unsigned m2 = __ballot_sync(0xffffffffu, a2);
        if (m2) {
            int s2 = __ffs(m2) - 1;
            if (lane == s2) {
                int sub;
                if      (u.x != 0.0f) sub = 0;
                else if (u.y != 0.0f) sub = 1;
                else if (u.z != 0.0f) sub = 2;
                else                  sub = 3;
                g_first_idx[warp] = base + (s2 << 2) + sub;
            }
            return;   // m2 is warp-uniform; all lanes exit together
        }
    }
    if (lane == 0) g_first_idx[warp] = -1;   // row never spikes
}

__global__ void __launch_bounds__(128)
first_spike_scatter(float* __restrict__ out, int rows)
{
    const int row = blockIdx.x * blockDim.x + threadIdx.x;
    if (row >= rows) return;
    const int idx = g_first_idx[row];
    if (idx >= 0) {
        out[(size_t)row * T + idx] = 1.0f;
    }
}

extern "C" void kernel_launch(void* const* d_in, const int* in_sizes, int n_in,
                              void* d_out, int out_size)
{
    const float* in = (const float*)d_in[0];
    float* out = (float*)d_out;
    const int rows = in_sizes[0] / T;   // 16384

    // One-time host-side resources (streams/events are not device memory).
    static cudaStream_t s_side = nullptr;
    static cudaEvent_t  ev_fork = nullptr, ev_join = nullptr;
    if (s_side == nullptr) {
        cudaStreamCreateWithFlags(&s_side, cudaStreamNonBlocking);
        cudaEventCreateWithFlags(&ev_fork, cudaEventDisableTiming);
        cudaEventCreateWithFlags(&ev_join, cudaEventDisableTiming);
    }

    // ---- fork ----
    cudaEventRecord(ev_fork, 0);
    cudaStreamWaitEvent(s_side, ev_fork, 0);

    // Branch A (main stream): contiguous full zero fill (~6.4 TB/s).
    cudaMemsetAsync(d_out, 0, (size_t)out_size * sizeof(float), 0);

    // Branch B (side stream): detection only -- reads input, writes scratch.
    {
        const int threads = 256;                                  // 8 warps/blk
        const int blocks  = (rows * 32 + threads - 1) / threads;  // 2048
        first_spike_detect<<<blocks, threads, 0, s_side>>>(in, rows);
    }

    // ---- join ----
    cudaEventRecord(ev_join, s_side);
    cudaStreamWaitEvent(0, ev_join, 0);

    // Scatter: one thread per row writes the single 1.0f.
    {
        const int threads = 128;
        const int blocks  = (rows + threads - 1) / threads;       // 128
        first_spike_scatter<<<blocks, threads>>>(out, rows);
    }
}

// round 11
// speedup vs baseline: 1.4504x; 1.4504x over previous
#include <cuda_runtime.h>
#include <cuda_bf16.h>
#include <cstdint>

// FirstSpikeDetector: out[b][t] = 1 iff spike_train[b][t] is the first nonzero
// in row b, else 0. Input values are exact 0.0f / 1.0f.
//
// R11 = R7's winning serial 2-node shape, detector trimmed.
//   Node 1: cudaMemsetAsync(out, 0, 128MB)  -- driver fill path, ~6.3 TB/s
//           cold / ~5.2 TB/s steady-state. This is the compulsory-write wall;
//           R1-R10 established no producer or overlap scheme beats it.
//   Node 2: detector -- one warp per row reads elements 0..127 (8MB total),
//           ballot-elects the first spike, writes ONE 1.0f. Rare rows
//           (P ~ 1.4e-6) continue scanning in 128-chunks.
// R11 tweaks: 1024-thread blocks (512 blocks vs 2048 -> less dispatch/tail),
// branchless sub-index via a 4-bit mask + __ffs instead of a dependent
// if-chain.
//
// Failed-and-falsified alternatives (do not retry): .cs/.ldcs hints (R2),
// zeros-before-ballot store bursts (R2/R3), persistent grids (R3), multi-row
// warp batching for the fused kernel (R4) and for the detector (R9),
// STG.256 (R6), 2D pitched memset (R8), fork/join overlap with the memset
// node (R8, R10 -- memset is a device-wide fill kernel; nothing overlaps).

static constexpr int T   = 2048;    // time steps per row
static constexpr int TV4 = T / 4;   // float4s per row (512)

__global__ void __launch_bounds__(1024)
first_spike_detect(const float* __restrict__ in, float* __restrict__ out, int rows)
{
    const int gtid = blockIdx.x * blockDim.x + threadIdx.x;
    const int warp = gtid >> 5;
    const int lane = gtid & 31;
    if (warp >= rows) return;

    const float4* __restrict__ row_in =
        reinterpret_cast<const float4*>(in) + (size_t)warp * TV4;
    float* __restrict__ row_out = out + (size_t)warp * T;

    // ---- scan elements 0..127 (1 x LDG.128 per lane) ----
    const float4 v = row_in[lane];
    const unsigned q = (v.x != 0.0f ? 1u : 0u) | (v.y != 0.0f ? 2u : 0u) |
                       (v.z != 0.0f ? 4u : 0u) | (v.w != 0.0f ? 8u : 0u);
    const unsigned m = __ballot_sync(0xffffffffu, q != 0u);

    if (m != 0u) {
        // Common path: first spike within elements 0..127.
        const int src = __ffs(m) - 1;
        if (lane == src) {
            const int sub = __ffs(q) - 1;          // branchless quadrant pick
            row_out[(src << 2) + sub] = 1.0f;      // zeros already laid by memset
        }
        return;
    }

    // Rare path (P ~ 1.4e-6 per row): keep scanning chunks of 128 elements.
    #pragma unroll 1
    for (int base = 128; base < T; base += 128) {
        const float4 u = row_in[(base >> 2) + lane];
        const unsigned q2 = (u.x != 0.0f ? 1u : 0u) | (u.y != 0.0f ? 2u : 0u) |
                            (u.z != 0.0f ? 4u : 0u) | (u.w != 0.0f ? 8u : 0u);
        const unsigned m2 = __ballot_sync(0xffffffffu, q2 != 0u);
        if (m2) {
            const int s2 = __ffs(m2) - 1;
            if (lane == s2) {
                const int sub = __ffs(q2) - 1;
                row_out[base + (s2 << 2) + sub] = 1.0f;
            }
            return;   // m2 is warp-uniform; all lanes exit together
        }
    }
    // No spike anywhere in the row: memset zeros are the correct output.
}

extern "C" void kernel_launch(void* const* d_in, const int* in_sizes, int n_in,
                              void* d_out, int out_size)
{
    const float* in = (const float*)d_in[0];
    float* out = (float*)d_out;
    const int rows = in_sizes[0] / T;   // 16384

    // Node 1: contiguous full zero fill (driver fill path).
    cudaMemsetAsync(d_out, 0, (size_t)out_size * sizeof(float), 0);

    // Node 2: sparse detector (reads ~8MB, writes ~64KB).
    const int threads = 1024;                                 // 32 warps/block
    const int blocks  = (rows * 32 + threads - 1) / threads;  // 512
    first_spike_detect<<<blocks, threads>>>(in, out, rows);
}

// round 12
// speedup vs baseline: 1.5702x; 1.0826x over previous
#include <cuda_runtime.h>
#include <cuda_bf16.h>
#include <cstdint>

// FirstSpikeDetector: out[b][t] = 1 iff spike_train[b][t] is the first nonzero
// in row b, else 0. Input values are exact 0.0f / 1.0f.
//
// R12 = R7's serial 2-node shape (full 1D memset ~6.3 TB/s, then a sparse
// detector writing ONE 1.0f per row) with the scan window halved:
//   - window = 64 elements (P(no spike in window) = 0.9^64 ~ 1.2e-3 ->
//     ~20 of 16384 rows take the rare path; each costs one extra chunk scan).
//   - one warp handles TWO rows: lanes 0-15 cover row A's elements 0..63
//     (one float4 per lane), lanes 16-31 cover row B's. Compulsory read
//     drops 8MB -> 4MB; 8192 warps = 1024 blocks x 256 thr = single wave.
// This attacks what R7/R9/R11 showed is the real detector binder: window
// bytes x latency over ~2 waves (the detector was pinned at 6.7-7.4us for
// every grid/block/MLP shape at window=128).
//
// Falsified (do not retry): .cs hints (R2), store-burst reorders (R2/R3),
// persistent grids (R3), rows/warp batching at window=128 (R4/R9), STG.256
// (R6), 2D pitched memset (R8), fork/join overlap with memset nodes (R8/R10
// -- memset is a device-wide fill kernel, nothing overlaps it).

static constexpr int T   = 2048;    // time steps per row
static constexpr int TV4 = T / 4;   // float4s per row (512)
static constexpr int WIN = 64;      // scan window (elements)

// Rare path: first spike not in elements 0..WIN-1 (or row never spikes).
// Full warp scans the row in 128-element chunks starting at WIN.
__device__ __noinline__ void rare_scan_and_store(
    const float4* __restrict__ row_in, float* __restrict__ row_out, int lane)
{
    #pragma unroll 1
    for (int base = WIN; base < T; base += 128) {
        const float4 u = row_in[(base >> 2) + lane];
        const unsigned q2 = (u.x != 0.0f ? 1u : 0u) | (u.y != 0.0f ? 2u : 0u) |
                            (u.z != 0.0f ? 4u : 0u) | (u.w != 0.0f ? 8u : 0u);
        const unsigned m2 = __ballot_sync(0xffffffffu, q2 != 0u);
        if (m2) {
            const int s2 = __ffs(m2) - 1;
            if (lane == s2) {
                row_out[base + (s2 << 2) + (__ffs(q2) - 1)] = 1.0f;
            }
            return;   // m2 is warp-uniform; all lanes exit together
        }
    }
    // No spike anywhere in the row: memset zeros are the correct output.
}

__global__ void __launch_bounds__(256)
first_spike_detect(const float* __restrict__ in, float* __restrict__ out,
                   int row_pairs)
{
    const int gtid = blockIdx.x * blockDim.x + threadIdx.x;
    const int warp = gtid >> 5;               // one warp = one row PAIR
    const int lane = gtid & 31;
    if (warp >= row_pairs) return;

    const int row0 = warp << 1;               // lanes 0-15 -> row0
    const int half = lane >> 4;               // lanes 16-31 -> row0+1
    const int sl   = lane & 15;               // sub-lane within the half

    const float4* __restrict__ in4 = reinterpret_cast<const float4*>(in);

    // Each lane loads one float4 of its row's 64-element window.
    const float4 v = in4[(size_t)(row0 + half) * TV4 + sl];
    const unsigned q = (v.x != 0.0f ? 1u : 0u) | (v.y != 0.0f ? 2u : 0u) |
                       (v.z != 0.0f ? 4u : 0u) | (v.w != 0.0f ? 8u : 0u);
    const unsigned m = __ballot_sync(0xffffffffu, q != 0u);

    const unsigned m0 = m & 0xFFFFu;          // row0's window mask
    const unsigned m1 = m >> 16;              // row1's window mask

    // ---- row 0 ----
    if (m0 != 0u) {
        const int s = __ffs(m0) - 1;          // electing lane (0..15)
        if (lane == s) {
            out[(size_t)row0 * T + (sl << 2) + (__ffs(q) - 1)] = 1.0f;
        }
    } else {
        rare_scan_and_store(in4 + (size_t)row0 * TV4,
                            out + (size_t)row0 * T, lane);
    }

    // ---- row 1 ----
    if (m1 != 0u) {
        const int s = 16 + __ffs(m1) - 1;     // electing lane (16..31)
        if (lane == s) {
            out[(size_t)(row0 + 1) * T + (sl << 2) + (__ffs(q) - 1)] = 1.0f;
        }
    } else {
        rare_scan_and_store(in4 + (size_t)(row0 + 1) * TV4,
                            out + (size_t)(row0 + 1) * T, lane);
    }
}

extern "C" void kernel_launch(void* const* d_in, const int* in_sizes, int n_in,
                              void* d_out, int out_size)
{
    const float* in = (const float*)d_in[0];
    float* out = (float*)d_out;
    const int rows = in_sizes[0] / T;        // 16384
    const int row_pairs = rows >> 1;         // 8192

    // Node 1: contiguous full zero fill (driver fill path).
    cudaMemsetAsync(d_out, 0, (size_t)out_size * sizeof(float), 0);

    // Node 2: sparse detector, 2 rows/warp, 64-element window (~4MB read).
    const int threads = 256;                                      // 8 warps/blk
    const int blocks  = (row_pairs * 32 + threads - 1) / threads; // 1024
    first_spike_detect<<<blocks, threads>>>(in, out, row_pairs);
}